// round 17
// baseline (speedup 1.0000x reference)
#include <cuda_runtime.h>
#include <cuda_bf16.h>
#include <cstdint>

// out[64,11008] = x[64,4096] @ (Wq*scale)^T + bias
// v11: v9's proven per-warp job (M64 x N16, v3 inner loop) in 4-warp BN=64
//      CTAs: regs back to ~110 -> 4 CTAs/SM (16 warps/SM) for latency hiding.
//      grid (172, 8) = 1376 CTAs. Atomic split-K epilogue, merged prep.

#define M_DIM 64
#define K_DIM 4096
#define N_DIM 11008

#define SPLITS 8
#define KSR    512          // real k per split
#define BKR    64           // real k per stage
#define NST    (KSR / BKR)  // 8 stages per CTA
#define BKE    128          // effective k per stage (hi/lo)
#define SA     136          // smem row stride in bf16 elems (128 + 8 pad)
#define BN     64           // CTA n-tile
#define THREADS 128

__device__ __align__(16) __nv_bfloat16 g_Axl[M_DIM * 8192];          // 1 MB

__device__ __forceinline__ unsigned pack_bf2(__nv_bfloat16 a, __nv_bfloat16 b) {
    return (unsigned)__bfloat16_as_ushort(a) | ((unsigned)__bfloat16_as_ushort(b) << 16);
}

// ---------------------------------------------------------------------------
// Kernel 1 (prep): every thread writes one float4 of out = bias; the first
// 65536 threads also convert one float4 of x into the permuted hi/lo layout.
// Layout per 16-real-k block j (32 keff slots): slot(sp,b,q,e)=sp*16+b*8+2q+e
//   real k = 16j + 4q + 2sp + e ; b=0 -> hi(x), b=1 -> lo(x)
// ---------------------------------------------------------------------------
__global__ void prep_kernel(const float* __restrict__ x,
                            const float* __restrict__ bias,
                            float* __restrict__ out) {
    int t = blockIdx.x * blockDim.x + threadIdx.x;   // 0..176127

    {
        int n4 = (4 * t) % N_DIM;
        float4 bs = *(const float4*)(bias + n4);
        ((float4*)out)[t] = bs;
    }

    if (t < 65536) {
        int m   = t >> 10;         // 0..63
        int idx = t & 1023;
        int j   = idx >> 2;        // 16-k block 0..255
        int q   = idx & 3;         // qp

        float4 f = *(const float4*)(x + m * K_DIM + j * 16 + q * 4);
        __nv_bfloat16 hx = __float2bfloat16_rn(f.x);
        __nv_bfloat16 hy = __float2bfloat16_rn(f.y);
        __nv_bfloat16 hz = __float2bfloat16_rn(f.z);
        __nv_bfloat16 hw = __float2bfloat16_rn(f.w);
        __nv_bfloat16 lx = __float2bfloat16_rn(f.x - __bfloat162float(hx));
        __nv_bfloat16 ly = __float2bfloat16_rn(f.y - __bfloat162float(hy));
        __nv_bfloat16 lz = __float2bfloat16_rn(f.z - __bfloat162float(hz));
        __nv_bfloat16 lw = __float2bfloat16_rn(f.w - __bfloat162float(hw));

        unsigned* base = (unsigned*)(g_Axl + m * 8192 + j * 32 + 2 * q);
        base[0]  = pack_bf2(hx, hy);   // sp0 hi
        base[4]  = pack_bf2(lx, ly);   // sp0 lo
        base[8]  = pack_bf2(hz, hw);   // sp1 hi
        base[12] = pack_bf2(lz, lw);   // sp1 lo
    }
}

// ---------------------------------------------------------------------------
// Kernel 2: split-K GEMM.  CTA: 4 warps, warp = M64 x N16 (v3's warp job).
// grid (172, 8).  A: cp.async double-buffer.  B: global -> regs (v3 schedule).
// Epilogue: atomicAdd(scale*acc) into bias-initialized out.
// ---------------------------------------------------------------------------
#define MMA16816(d, a0, a1, a2, a3, b)                                          \
    asm volatile(                                                               \
        "mma.sync.aligned.m16n8k16.row.col.f32.bf16.bf16.f32 "                  \
        "{%0,%1,%2,%3}, {%4,%5,%6,%7}, {%8,%9}, {%0,%1,%2,%3};\n"               \
        : "+f"(d[0]), "+f"(d[1]), "+f"(d[2]), "+f"(d[3])                        \
        : "r"(a0), "r"(a1), "r"(a2), "r"(a3), "r"(b), "r"(b))

// A stage copy: 64 rows x 128 keff bf16 = 1024 x 16B chunks; 128 thr x 8.
__device__ __forceinline__ void issue_a(uint32_t adst0, const __nv_bfloat16* agsrc,
                                        int kt, int buf) {
    #pragma unroll
    for (int j = 0; j < 8; ++j) {
        uint32_t d = adst0 + buf * (M_DIM * SA * 2) + j * (8 * SA * 2);
        const void* s = agsrc + kt * BKE + (size_t)j * 8 * 8192;
        asm volatile("cp.async.ca.shared.global [%0], [%1], 16;\n"
                     :: "r"(d), "l"(s));
    }
}

__global__ __launch_bounds__(THREADS, 4)
void qgemm_kernel(const int* __restrict__ wq,
                  const float* __restrict__ wscale,
                  float* __restrict__ out) {
    __shared__ __align__(16) __nv_bfloat16 As[2][M_DIM * SA];

    const int tid  = threadIdx.x;
    const int lane = tid & 31;
    const int wid  = tid >> 5;      // 0..3 = n-tile (16 cols each)
    const int qp   = lane & 3;
    const int g    = lane >> 2;
    const int bn0   = blockIdx.x * BN;
    const int split = blockIdx.y;

    uint32_t sb;
    { void* p = (void*)As;
      asm("{.reg .u64 t; cvta.to.shared.u64 t, %1; cvt.u32.u64 %0, t;}"
          : "=r"(sb) : "l"(p)); }

    // ---- A cp.async mapping: thread copies 8 x 16B per stage
    const int acol = tid & 15;            // 16B chunk within keff-128 row
    const int arow = tid >> 4;            // base row (8 rows), +8 per j
    const __nv_bfloat16* agsrc = g_Axl + (size_t)arow * 8192 + split * (KSR * 2) + acol * 8;
    const uint32_t adst0 = sb + (uint32_t)((arow * SA + acol * 8) * 2);

    // ---- B pointers: nfrag f row = bn0 + wid*16 + f*8 + g   (v3 layout)
    const int* wg0 = wq + (size_t)(bn0 + wid * 16 + g) * K_DIM + split * KSR + 4 * qp;
    const int* wg1 = wg0 + (size_t)8 * K_DIM;

    int4 Bn[2][4];

    // ---- prologue: A stage 0; B stage 0
    issue_a(adst0, agsrc, 0, 0);
    asm volatile("cp.async.commit_group;\n");
    #pragma unroll
    for (int j = 0; j < 4; ++j) {
        Bn[0][j] = *(const int4*)(wg0 + 16 * j);
        Bn[1][j] = *(const int4*)(wg1 + 16 * j);
    }

    float acc[4][2][4];
    #pragma unroll
    for (int a = 0; a < 4; ++a)
        #pragma unroll
        for (int b = 0; b < 2; ++b)
            #pragma unroll
            for (int c = 0; c < 4; ++c) acc[a][b][c] = 0.0f;

    const uint32_t aptr = sb + (uint32_t)(((lane & 15) * SA + (lane >> 4) * 8) * 2);

    for (int kt = 0; kt < NST; ++kt) {
        if (kt + 1 < NST) issue_a(adst0, agsrc, kt + 1, (kt + 1) & 1);
        asm volatile("cp.async.commit_group;\n");
        if (kt + 1 < NST) asm volatile("cp.async.wait_group 1;\n");
        else              asm volatile("cp.async.wait_group 0;\n");
        __syncthreads();

        const uint32_t abuf = aptr + (kt & 1) * (M_DIM * SA * 2);
        const int* nw0 = wg0 + (kt + 1) * BKR;
        const int* nw1 = wg1 + (kt + 1) * BKR;
        const bool pf = (kt + 1 < NST);

        #pragma unroll
        for (int s = 0; s < 8; ++s) {
            const int j = s >> 1;
            int v0x, v0y, v1x, v1y;
            if ((s & 1) == 0) { v0x = Bn[0][j].x; v0y = Bn[0][j].y;
                                v1x = Bn[1][j].x; v1y = Bn[1][j].y; }
            else              { v0x = Bn[0][j].z; v0y = Bn[0][j].w;
                                v1x = Bn[1][j].z; v1y = Bn[1][j].w; }
            float f0 = (float)v0x, f1 = (float)v0y;
            float f2 = (float)v1x, f3 = (float)v1y;
            unsigned bb0, bb1;
            asm("cvt.rn.bf16x2.f32 %0, %1, %2;" : "=r"(bb0) : "f"(f1), "f"(f0));
            asm("cvt.rn.bf16x2.f32 %0, %1, %2;" : "=r"(bb1) : "f"(f3), "f"(f2));

            // refill Bn[*][j] for next stage once consumed (odd s)
            if ((s & 1) == 1 && pf) {
                Bn[0][j] = *(const int4*)(nw0 + 16 * j);
                Bn[1][j] = *(const int4*)(nw1 + 16 * j);
            }

            #pragma unroll
            for (int fm = 0; fm < 4; ++fm) {
                unsigned a0, a1, a2, a3;
                asm volatile(
                    "ldmatrix.sync.aligned.m8n8.x4.shared.b16 {%0,%1,%2,%3}, [%4];\n"
                    : "=r"(a0), "=r"(a1), "=r"(a2), "=r"(a3)
                    : "r"(abuf + fm * (16 * SA * 2) + s * 32));
                MMA16816(acc[fm][0], a0, a1, a2, a3, bb0);
                MMA16816(acc[fm][1], a0, a1, a2, a3, bb1);
            }
        }
        __syncthreads();
    }

    // ---- epilogue: atomicAdd scale*acc into bias-initialized out
    const float sc = wscale[0];
    #pragma unroll
    for (int fm = 0; fm < 4; ++fm) {
        const int m0 = fm * 16 + g;
        #pragma unroll
        for (int fn = 0; fn < 2; ++fn) {
            const int n = bn0 + wid * 16 + fn * 8 + 2 * qp;
            atomicAdd(out + (size_t)m0 * N_DIM + n,           sc * acc[fm][fn][0]);
            atomicAdd(out + (size_t)m0 * N_DIM + n + 1,       sc * acc[fm][fn][1]);
            atomicAdd(out + (size_t)(m0 + 8) * N_DIM + n,     sc * acc[fm][fn][2]);
            atomicAdd(out + (size_t)(m0 + 8) * N_DIM + n + 1, sc * acc[fm][fn][3]);
        }
    }
}

extern "C" void kernel_launch(void* const* d_in, const int* in_sizes, int n_in,
                              void* d_out, int out_size) {
    const float* x      = (const float*)d_in[0];
    const int*   wq     = (const int*)  d_in[1];
    const float* wscale = (const float*)d_in[2];
    const float* bias   = (const float*)d_in[3];
    float*       out    = (float*)d_out;

    prep_kernel<<<688, 256>>>(x, bias, out);
    qgemm_kernel<<<dim3(N_DIM / BN, SPLITS), THREADS>>>(wq, wscale, out);
}